// round 4
// baseline (speedup 1.0000x reference)
#include <cuda_runtime.h>
#include <cstdint>

#define MAPSZ 38809      // 197*197
#define NP    196        // 14*14 patches
#define HW    784        // 28*28
#define THRPT 160

__global__ __launch_bounds__(1024, 1)
void maskgen_kernel(const float* __restrict__ att, float* __restrict__ out)
{
    __shared__ float sh_partial[HW];   // per-(q,p) partial sums
    __shared__ float sh_a14[NP];       // 14x14 attention means
    __shared__ float sh_red[256];      // threshold reduction
    __shared__ int   sh_lab[HW];       // CCL labels (HW = background)
    __shared__ int   sh_cnt[HW];       // per-label counts
    __shared__ int   sh_wsum[32], sh_wpre[32];
    __shared__ int   sh_changed, sh_key, sh_total;
    __shared__ float sh_thr;

    const int b   = blockIdx.x;
    const int tid = threadIdx.x;

    // ---------- Phase A: a14[p] = mean over 144 maps of att[i,b,j,0,1+p] ----------
    // map linear index = i*384 + b*12 + j; tid<784: q=tid/196 picks 36 maps (i in [3q,3q+2]).
    if (tid < HW) {
        const int q = tid / NP;
        const int p = tid - q * NP;
        const float* base = att + (size_t)(q * 1152 + b * 12) * MAPSZ + 1 + p;
        float s0 = 0.f, s1 = 0.f, s2 = 0.f, s3 = 0.f;
        #pragma unroll
        for (int k = 0; k < 36; k += 4) {
            s0 += __ldg(base + (size_t)(((k + 0) / 12) * 384 + (k + 0) % 12) * MAPSZ);
            s1 += __ldg(base + (size_t)(((k + 1) / 12) * 384 + (k + 1) % 12) * MAPSZ);
            s2 += __ldg(base + (size_t)(((k + 2) / 12) * 384 + (k + 2) % 12) * MAPSZ);
            s3 += __ldg(base + (size_t)(((k + 3) / 12) * 384 + (k + 3) % 12) * MAPSZ);
        }
        sh_partial[tid] = (s0 + s1) + (s2 + s3);
    }
    __syncthreads();

    if (tid < NP) {
        float v = (sh_partial[tid] + sh_partial[tid + NP])
                + (sh_partial[tid + 2 * NP] + sh_partial[tid + 3 * NP]);
        sh_a14[tid] = v / 144.0f;
    }
    __syncthreads();

    // ---------- threshold = mean of a14 (== mean of 28x28 upsample) ----------
    if (tid < 256) sh_red[tid] = (tid < NP) ? sh_a14[tid] : 0.f;
    __syncthreads();
    for (int s = 128; s > 0; s >>= 1) {
        if (tid < s) sh_red[tid] += sh_red[tid + s];
        __syncthreads();
    }
    if (tid == 0) {
        sh_thr = sh_red[0] / 196.0f;
        sh_key = 0;
        sh_changed = 0;
    }
    __syncthreads();
    const float thr = sh_thr;

    // ---------- mask (nearest 2x upsample) + label init ----------
    if (tid < HW) {
        int y = tid / 28, x = tid - y * 28;
        bool m = sh_a14[(y >> 1) * 14 + (x >> 1)] > thr;
        sh_lab[tid] = m ? tid : HW;
        sh_cnt[tid] = 0;
    }
    __syncthreads();

    // ---------- CCL: neighbor-min + pointer jumping to fixed point ----------
    // Fixed point == per-component min flat index == reference's 784 Jacobi iters.
    // Monotone-min: in-place races are benign (any read is a valid upper bound).
    for (int it = 0; it < HW; ++it) {
        bool ch = false;
        if (tid < HW && sh_lab[tid] < HW) {
            int c = tid;
            int v = sh_lab[c];
            int y = c / 28, x = c - y * 28;
            if (y > 0)  v = min(v, sh_lab[c - 28]);
            if (y < 27) v = min(v, sh_lab[c + 28]);
            if (x > 0)  v = min(v, sh_lab[c - 1]);
            if (x < 27) v = min(v, sh_lab[c + 1]);
            v = sh_lab[v];   // pointer jump (label values are fg seed indices)
            v = sh_lab[v];
            if (v < sh_lab[c]) { sh_lab[c] = v; ch = true; }
        }
        if (ch) sh_changed = 1;
        __syncthreads();
        int done = (sh_changed == 0);
        __syncthreads();
        if (done) break;
        if (tid == 0) sh_changed = 0;
        __syncthreads();
    }

    // ---------- component areas, argmax (ties -> smallest label) ----------
    if (tid < HW && sh_lab[tid] < HW) atomicAdd(&sh_cnt[sh_lab[tid]], 1);
    __syncthreads();
    if (tid < HW && sh_cnt[tid] > 0) {
        int key = (sh_cnt[tid] << 10) | (1023 - tid);   // count<=784, label<784
        atomicMax(&sh_key, key);
    }
    __syncthreads();
    const int maxArea = sh_key >> 10;
    const int maxLab  = 1023 - (sh_key & 1023);
    const bool keep   = (maxArea >= THRPT);

    int f = 0;
    if (tid < HW) f = keep ? (sh_lab[tid] == maxLab) : (sh_lab[tid] < HW);

    // ---------- stable "fg indices first, then bg" compaction ----------
    unsigned bal = __ballot_sync(0xFFFFFFFFu, f);
    const int lane = tid & 31, w = tid >> 5;
    const int lanepre = __popc(bal & ((1u << lane) - 1));
    if (lane == 0) sh_wsum[w] = __popc(bal);
    __syncthreads();
    if (w == 0) {
        int v = sh_wsum[lane];
        int inc = v;
        #pragma unroll
        for (int off = 1; off < 32; off <<= 1) {
            int t = __shfl_up_sync(0xFFFFFFFFu, inc, off);
            if (lane >= off) inc += t;
        }
        sh_wpre[lane] = inc - v;
        if (lane == 31) sh_total = inc;   // total fg count
    }
    __syncthreads();

    if (tid < HW) {
        int fgpre = sh_wpre[w] + lanepre;
        int pos = f ? fgpre : (sh_total + (tid - fgpre));
        out[b * HW + pos] = (float)(tid + 1);   // __output__ is float32!
    }
}

extern "C" void kernel_launch(void* const* d_in, const int* in_sizes, int n_in,
                              void* d_out, int out_size)
{
    (void)in_sizes; (void)n_in; (void)out_size;
    const float* att = (const float*)d_in[0];
    float* out = (float*)d_out;
    maskgen_kernel<<<32, 1024>>>(att, out);
}